// round 5
// baseline (speedup 1.0000x reference)
#include <cuda_runtime.h>
#include <cuda_bf16.h>
#include <math.h>

// ---------------------------------------------------------------------------
// Problem constants
// ---------------------------------------------------------------------------
#define BATCH   2
#define LSEQ    4096
#define DMODEL  2048
#define BL      (BATCH * LSEQ)          // 8192
#define DTRANK  128
#define DSTATE  16
#define OCOLS   (DTRANK + 2 * DSTATE)   // 160
#define LOG2E   1.4426950408889634f

// ---------------------------------------------------------------------------
// Scratch (device globals; allocation-free per harness rules)
// ---------------------------------------------------------------------------
__device__ float    g_Wxq [OCOLS * DMODEL];      // quantized Wx
__device__ float    g_Wdtq[DMODEL * DTRANK];     // quantized Wdt
__device__ float    g_A2  [DMODEL * DSTATE];     // -exp(fq(A_log)) * log2(e)
__device__ float    g_Dq  [DMODEL];              // fq(Dskip)
__device__ float    g_xdbl[BL * OCOLS];          // GEMM1 out
__device__ float    g_dt  [BL * DMODEL];         // GEMM2 out -> softplus(fq) in place
__device__ float    g_uq  [BL * DMODEL];         // fq(x)
__device__ float    g_Bq  [BL * DSTATE];
__device__ float    g_Cq  [BL * DSTATE];
__device__ unsigned g_maxbits[4];                // 0:|x| 1:|dts| 2:|Bs| 3:|Cs+prompt|

// ---------------------------------------------------------------------------
// Helpers
// ---------------------------------------------------------------------------
__device__ __forceinline__ float ex2f(float x) {
    float r;
    asm("ex2.approx.ftz.f32 %0, %1;" : "=f"(r) : "f"(x));
    return r;
}

__device__ __forceinline__ float fq_val(float x, float s) {
    // clip(round(x/s), -128, 127) * s ; rintf = round-half-even (jnp.round)
    return fminf(fmaxf(rintf(x / s), -128.0f), 127.0f) * s;
}

// block-wide max reduction; all threads receive the result
__device__ __forceinline__ float block_max(float v) {
    __shared__ float red[32];
    __syncthreads();
    #pragma unroll
    for (int o = 16; o; o >>= 1)
        v = fmaxf(v, __shfl_xor_sync(0xffffffffu, v, o));
    int w = threadIdx.x >> 5, nl = threadIdx.x & 31;
    if (nl == 0) red[w] = v;
    __syncthreads();
    int nw = blockDim.x >> 5;
    if (w == 0) {
        float m = (nl < nw) ? red[nl] : 0.0f;
        #pragma unroll
        for (int o = 16; o; o >>= 1)
            m = fmaxf(m, __shfl_xor_sync(0xffffffffu, m, o));
        if (nl == 0) red[0] = m;
    }
    __syncthreads();
    return red[0];
}

__device__ __forceinline__ void cp16(void* dst, const void* src) {
    unsigned s = (unsigned)__cvta_generic_to_shared(dst);
    asm volatile("cp.async.cg.shared.global [%0], [%1], 16;" :: "r"(s), "l"(src));
}

// ---------------------------------------------------------------------------
// Prep kernels
// ---------------------------------------------------------------------------
__global__ void k_init() {
    if (threadIdx.x < 4) g_maxbits[threadIdx.x] = 0u;
}

// per-output-channel weight fake-quant: one block per row
__global__ void k_quant_rows(const float* __restrict__ src, float* __restrict__ dst, int K) {
    int row = blockIdx.x;
    const float* s = src + (size_t)row * K;
    float m = 0.0f;
    for (int i = threadIdx.x; i < K; i += blockDim.x) m = fmaxf(m, fabsf(s[i]));
    m = block_max(m);
    float sc = fmaxf(m / 127.0f, 1e-8f);
    float* d = dst + (size_t)row * K;
    for (int i = threadIdx.x; i < K; i += blockDim.x) d[i] = fq_val(s[i], sc);
}

// A_log: per-row (16 cols) quant, then A2 = -exp(q)*log2e.  8 rows per block.
__global__ void k_prep_A(const float* __restrict__ A_log) {
    int r = blockIdx.x * 8 + (threadIdx.x >> 4);
    int j = threadIdx.x & 15;
    float v = A_log[r * DSTATE + j];
    float m = fabsf(v);
    #pragma unroll
    for (int o = 8; o; o >>= 1) m = fmaxf(m, __shfl_xor_sync(0xffffffffu, m, o));
    float s = fmaxf(m / 127.0f, 1e-8f);
    float q = fq_val(v, s);
    g_A2[r * DSTATE + j] = -expf(q) * LOG2E;
}

__global__ void k_quant_D(const float* __restrict__ Dskip) {
    float m = 0.0f;
    for (int i = threadIdx.x; i < DMODEL; i += blockDim.x) m = fmaxf(m, fabsf(Dskip[i]));
    m = block_max(m);
    float s = fmaxf(m / 127.0f, 1e-8f);
    for (int i = threadIdx.x; i < DMODEL; i += blockDim.x) g_Dq[i] = fq_val(Dskip[i], s);
}

// ---------------------------------------------------------------------------
// Abs-max passes (atomicMax on float bit pattern; all values >= 0)
// ---------------------------------------------------------------------------
__device__ __forceinline__ void absmax_body(const float4* __restrict__ p, int n4, int slot) {
    float m = 0.0f;
    for (int i = blockIdx.x * blockDim.x + threadIdx.x; i < n4; i += gridDim.x * blockDim.x) {
        float4 v = p[i];
        m = fmaxf(m, fmaxf(fmaxf(fabsf(v.x), fabsf(v.y)), fmaxf(fabsf(v.z), fabsf(v.w))));
    }
    m = block_max(m);
    if (threadIdx.x == 0) atomicMax(&g_maxbits[slot], __float_as_uint(m));
}

__global__ void k_absmax_x(const float4* __restrict__ x, int n4) { absmax_body(x, n4, 0); }
__global__ void k_absmax_dt() { absmax_body((const float4*)g_dt, BL * DMODEL / 4, 1); }

__global__ void k_absmax_BC(const float* __restrict__ prompt) {
    int row = blockIdx.x * blockDim.x + threadIdx.x;   // 64*128 = 8192 rows
    const float* xr = g_xdbl + (size_t)row * OCOLS;
    const float* pr = prompt + (size_t)row * DSTATE;
    float mB = 0.0f, mC = 0.0f;
    #pragma unroll
    for (int j = 0; j < DSTATE; j += 4) {
        float4 bv = *(const float4*)&xr[DTRANK + j];
        float4 cv = *(const float4*)&xr[DTRANK + DSTATE + j];
        float4 pv = *(const float4*)&pr[j];
        mB = fmaxf(mB, fmaxf(fmaxf(fabsf(bv.x), fabsf(bv.y)), fmaxf(fabsf(bv.z), fabsf(bv.w))));
        float c0 = cv.x + pv.x, c1 = cv.y + pv.y, c2 = cv.z + pv.z, c3 = cv.w + pv.w;
        mC = fmaxf(mC, fmaxf(fmaxf(fabsf(c0), fabsf(c1)), fmaxf(fabsf(c2), fabsf(c3))));
    }
    float rB = block_max(mB);
    if (threadIdx.x == 0) atomicMax(&g_maxbits[2], __float_as_uint(rB));
    float rC = block_max(mC);
    if (threadIdx.x == 0) atomicMax(&g_maxbits[3], __float_as_uint(rC));
}

// ---------------------------------------------------------------------------
// Elementwise quant passes
// ---------------------------------------------------------------------------
__global__ void k_uq(const float4* __restrict__ x, int n4) {
    float s = fmaxf(__uint_as_float(g_maxbits[0]) / 127.0f, 1e-8f);
    float4* o = (float4*)g_uq;
    for (int i = blockIdx.x * blockDim.x + threadIdx.x; i < n4; i += gridDim.x * blockDim.x) {
        float4 v = x[i];
        v.x = fq_val(v.x, s); v.y = fq_val(v.y, s);
        v.z = fq_val(v.z, s); v.w = fq_val(v.w, s);
        o[i] = v;
    }
}

__device__ __forceinline__ float softplusf(float x) {
    return fmaxf(x, 0.0f) + log1pf(expf(-fabsf(x)));
}

__global__ void k_dt_transform() {
    float s = fmaxf(__uint_as_float(g_maxbits[1]) / 127.0f, 1e-8f);
    float4* p = (float4*)g_dt;
    int n4 = BL * DMODEL / 4;
    for (int i = blockIdx.x * blockDim.x + threadIdx.x; i < n4; i += gridDim.x * blockDim.x) {
        float4 v = p[i];
        v.x = softplusf(fq_val(v.x, s)); v.y = softplusf(fq_val(v.y, s));
        v.z = softplusf(fq_val(v.z, s)); v.w = softplusf(fq_val(v.w, s));
        p[i] = v;
    }
}

__global__ void k_quant_BC(const float* __restrict__ prompt) {
    int row = blockIdx.x * blockDim.x + threadIdx.x;   // 8192 rows
    float sB = fmaxf(__uint_as_float(g_maxbits[2]) / 127.0f, 1e-8f);
    float sC = fmaxf(__uint_as_float(g_maxbits[3]) / 127.0f, 1e-8f);
    const float* xr = g_xdbl + (size_t)row * OCOLS;
    const float* pr = prompt + (size_t)row * DSTATE;
    #pragma unroll
    for (int j = 0; j < DSTATE; j += 4) {
        float4 bv = *(const float4*)&xr[DTRANK + j];
        float4 cv = *(const float4*)&xr[DTRANK + DSTATE + j];
        float4 pv = *(const float4*)&pr[j];
        float4 ob, oc;
        ob.x = fq_val(bv.x, sB); ob.y = fq_val(bv.y, sB);
        ob.z = fq_val(bv.z, sB); ob.w = fq_val(bv.w, sB);
        oc.x = fq_val(cv.x + pv.x, sC); oc.y = fq_val(cv.y + pv.y, sC);
        oc.z = fq_val(cv.z + pv.z, sC); oc.w = fq_val(cv.w + pv.w, sC);
        *(float4*)&g_Bq[(size_t)row * DSTATE + j] = ob;
        *(float4*)&g_Cq[(size_t)row * DSTATE + j] = oc;
    }
}

// ---------------------------------------------------------------------------
// GEMM1: x_dbl[8192,160] = X[8192,2048] @ Wxq[160,2048]^T
// block = 320 threads, tile 64 rows x 160 cols, K-step 32
// ---------------------------------------------------------------------------
__global__ __launch_bounds__(320, 1) void k_gemm1(const float* __restrict__ X) {
    __shared__ float As[32 * 68];    // [k][row], stride 68 (16B-aligned rows)
    __shared__ float Bs[32 * 160];   // [k][col]
    int tid = threadIdx.x;
    int tx = tid % 20;               // 8 cols each -> 160
    int ty = tid / 20;               // 4 rows each -> 64
    int r0 = blockIdx.x * 64;
    float c[4][8];
    #pragma unroll
    for (int i = 0; i < 4; i++)
        #pragma unroll
        for (int j = 0; j < 8; j++) c[i][j] = 0.0f;

    for (int k0 = 0; k0 < DMODEL; k0 += 32) {
        __syncthreads();
        for (int idx = tid; idx < 512; idx += 320) {          // A: 64 rows x 8 f4
            int r = idx >> 3, kk = (idx & 7) << 2;
            float4 v = *(const float4*)&X[(size_t)(r0 + r) * DMODEL + k0 + kk];
            As[(kk + 0) * 68 + r] = v.x; As[(kk + 1) * 68 + r] = v.y;
            As[(kk + 2) * 68 + r] = v.z; As[(kk + 3) * 68 + r] = v.w;
        }
        for (int idx = tid; idx < 1280; idx += 320) {         // B: 160 cols x 8 f4
            int cc = idx >> 3, kk = (idx & 7) << 2;
            float4 v = *(const float4*)&g_Wxq[(size_t)cc * DMODEL + k0 + kk];
            Bs[(kk + 0) * 160 + cc] = v.x; Bs[(kk + 1) * 160 + cc] = v.y;
            Bs[(kk + 2) * 160 + cc] = v.z; Bs[(kk + 3) * 160 + cc] = v.w;
        }
        __syncthreads();
        #pragma unroll
        for (int k = 0; k < 32; k++) {
            float4 a  = *(const float4*)&As[k * 68 + ty * 4];
            float4 b0 = *(const float4*)&Bs[k * 160 + tx * 8];
            float4 b1 = *(const float4*)&Bs[k * 160 + tx * 8 + 4];
            float av[4] = {a.x, a.y, a.z, a.w};
            float bv[8] = {b0.x, b0.y, b0.z, b0.w, b1.x, b1.y, b1.z, b1.w};
            #pragma unroll
            for (int i = 0; i < 4; i++)
                #pragma unroll
                for (int j = 0; j < 8; j++) c[i][j] = fmaf(av[i], bv[j], c[i][j]);
        }
    }
    #pragma unroll
    for (int i = 0; i < 4; i++) {
        float4 o0 = {c[i][0], c[i][1], c[i][2], c[i][3]};
        float4 o1 = {c[i][4], c[i][5], c[i][6], c[i][7]};
        size_t base = (size_t)(r0 + ty * 4 + i) * OCOLS + tx * 8;
        *(float4*)&g_xdbl[base]     = o0;
        *(float4*)&g_xdbl[base + 4] = o1;
    }
}

// ---------------------------------------------------------------------------
// GEMM2: dts[8192,2048] = x_dbl[:, :128] @ Wdtq[2048,128]^T + bdt
// block = 256 threads, tile 64 x 128, K-step 32 (K=128)
// ---------------------------------------------------------------------------
__global__ __launch_bounds__(256, 1) void k_gemm2(const float* __restrict__ bdt) {
    __shared__ float As[32 * 68];
    __shared__ float Bs[32 * 128];
    int tid = threadIdx.x;
    int tx = tid % 16;               // 8 cols -> 128
    int ty = tid / 16;               // 4 rows -> 64
    int r0 = blockIdx.x * 64;
    int c0 = blockIdx.y * 128;
    float c[4][8];
    #pragma unroll
    for (int i = 0; i < 4; i++)
        #pragma unroll
        for (int j = 0; j < 8; j++) c[i][j] = 0.0f;

    for (int k0 = 0; k0 < DTRANK; k0 += 32) {
        __syncthreads();
        for (int idx = tid; idx < 512; idx += 256) {          // A from x_dbl
            int r = idx >> 3, kk = (idx & 7) << 2;
            float4 v = *(const float4*)&g_xdbl[(size_t)(r0 + r) * OCOLS + k0 + kk];
            As[(kk + 0) * 68 + r] = v.x; As[(kk + 1) * 68 + r] = v.y;
            As[(kk + 2) * 68 + r] = v.z; As[(kk + 3) * 68 + r] = v.w;
        }
        for (int idx = tid; idx < 1024; idx += 256) {         // B from Wdtq
            int cc = idx >> 3, kk = (idx & 7) << 2;
            float4 v = *(const float4*)&g_Wdtq[(size_t)(c0 + cc) * DTRANK + k0 + kk];
            Bs[(kk + 0) * 128 + cc] = v.x; Bs[(kk + 1) * 128 + cc] = v.y;
            Bs[(kk + 2) * 128 + cc] = v.z; Bs[(kk + 3) * 128 + cc] = v.w;
        }
        __syncthreads();
        #pragma unroll
        for (int k = 0; k < 32; k++) {
            float4 a  = *(const float4*)&As[k * 68 + ty * 4];
            float4 b0 = *(const float4*)&Bs[k * 128 + tx * 8];
            float4 b1 = *(const float4*)&Bs[k * 128 + tx * 8 + 4];
            float av[4] = {a.x, a.y, a.z, a.w};
            float bv[8] = {b0.x, b0.y, b0.z, b0.w, b1.x, b1.y, b1.z, b1.w};
            #pragma unroll
            for (int i = 0; i < 4; i++)
                #pragma unroll
                for (int j = 0; j < 8; j++) c[i][j] = fmaf(av[i], bv[j], c[i][j]);
        }
    }
    float bias[8];
    #pragma unroll
    for (int j = 0; j < 8; j++) bias[j] = bdt[c0 + tx * 8 + j];
    #pragma unroll
    for (int i = 0; i < 4; i++) {
        float4 o0 = {c[i][0] + bias[0], c[i][1] + bias[1], c[i][2] + bias[2], c[i][3] + bias[3]};
        float4 o1 = {c[i][4] + bias[4], c[i][5] + bias[5], c[i][6] + bias[6], c[i][7] + bias[7]};
        size_t base = (size_t)(r0 + ty * 4 + i) * DMODEL + c0 + tx * 8;
        *(float4*)&g_dt[base]     = o0;
        *(float4*)&g_dt[base + 4] = o1;
    }
}

// ---------------------------------------------------------------------------
// Selective scan: 128 blocks x 128 threads. Block = 32 channels (4 lanes x 4
// states each). Double-buffered cp.async staging of 64-step tiles.
// ---------------------------------------------------------------------------
#define SCT 64
#define SCC 32
// dynamic smem layout (floats):
//   sdt[2][SCT*SCC]  @0      su[2][SCT*SCC] @4096
//   sB [2][SCT*16]   @8192   sC[2][SCT*16]  @10240
//   sy [SCT*SCC]     @12288  sD[32]         @14336
#define SCAN_SMEM_FLOATS 14368

__device__ __forceinline__ void scan_issue(float* sm, int buf, int tid,
                                           size_t rowBase, int d0) {
    float* sdt = sm + buf * (SCT * SCC);
    float* su  = sm + 4096 + buf * (SCT * SCC);
    float* sB  = sm + 8192 + buf * (SCT * 16);
    float* sC  = sm + 10240 + buf * (SCT * 16);
    #pragma unroll
    for (int i = 0; i < 4; i++) {
        int idx = tid + 128 * i;
        int t = idx >> 3, c4 = (idx & 7) << 2;
        size_t g = (rowBase + t) * DMODEL + d0 + c4;
        cp16(&sdt[t * SCC + c4], &g_dt[g]);
        cp16(&su [t * SCC + c4], &g_uq[g]);
    }
    #pragma unroll
    for (int i = 0; i < 2; i++) {
        int idx = tid + 128 * i;
        int t = idx >> 2, j4 = (idx & 3) << 2;
        size_t g = (rowBase + t) * DSTATE + j4;
        cp16(&sB[t * 16 + j4], &g_Bq[g]);
        cp16(&sC[t * 16 + j4], &g_Cq[g]);
    }
    asm volatile("cp.async.commit_group;\n" ::: "memory");
}

__global__ __launch_bounds__(128, 1) void k_scan(float* __restrict__ out) {
    extern __shared__ float sm[];
    float* sy = sm + 12288;
    float* sD = sm + 14336;
    int tid = threadIdx.x;
    int b  = blockIdx.x >> 6;            // 128 blocks: 64 per batch
    int d0 = (blockIdx.x & 63) * SCC;
    int ch = tid >> 2, ln = tid & 3;
    int d  = d0 + ch;
    float4 A2r = *(const float4*)&g_A2[d * DSTATE + ln * 4];
    if (tid < SCC) sD[tid] = g_Dq[d0 + tid];
    float h0 = 0.f, h1 = 0.f, h2 = 0.f, h3 = 0.f;
    size_t batchRow = (size_t)b * LSEQ;

    scan_issue(sm, 0, tid, batchRow, d0);

    for (int tile = 0; tile < LSEQ / SCT; tile++) {
        int buf = tile & 1;
        int t0 = tile * SCT;
        if (tile < LSEQ / SCT - 1) {
            scan_issue(sm, buf ^ 1, tid, batchRow + t0 + SCT, d0);
            asm volatile("cp.async.wait_group 1;\n" ::: "memory");
        } else {
            asm volatile("cp.async.wait_group 0;\n" ::: "memory");
        }
        __syncthreads();

        const float* dtp = sm + buf * (SCT * SCC);
        const float* up  = sm + 4096 + buf * (SCT * SCC);
        const float* Bp  = sm + 8192 + buf * (SCT * 16);
        const float* Cp  = sm + 10240 + buf * (SCT * 16);

        #pragma unroll 4
        for (int t = 0; t < SCT; t++) {
            float dtv = dtp[t * SCC + ch];
            float uq  = up [t * SCC + ch];
            float du  = dtv * uq;
            float4 Bv = *(const float4*)&Bp[t * 16 + ln * 4];
            float4 Cv = *(const float4*)&Cp[t * 16 + ln * 4];
            h0 = fmaf(ex2f(dtv * A2r.x), h0, du * Bv.x);
            h1 = fmaf(ex2f(dtv * A2r.y), h1, du * Bv.y);
            h2 = fmaf(ex2f(dtv * A2r.z), h2, du * Bv.z);
            h3 = fmaf(ex2f(dtv * A2r.w), h3, du * Bv.w);
            float y = fmaf(h3, Cv.w, fmaf(h2, Cv.z, fmaf(h1, Cv.y, h0 * Cv.x)));
            y += __shfl_xor_sync(0xffffffffu, y, 1);
            y += __shfl_xor_sync(0xffffffffu, y, 2);
            if (ln == 0) sy[t * SCC + ch] = y;
        }
        __syncthreads();

        // coalesced store: out = y + u_q * D_q
        #pragma unroll
        for (int i = 0; i < 4; i++) {
            int idx = tid + 128 * i;
            int t = idx >> 3, c4 = (idx & 7) << 2;
            float4 y  = *(const float4*)&sy[t * SCC + c4];
            float4 uq = *(const float4*)&up[t * SCC + c4];
            float4 Dv = *(const float4*)&sD[c4];
            y.x = fmaf(uq.x, Dv.x, y.x); y.y = fmaf(uq.y, Dv.y, y.y);
            y.z = fmaf(uq.z, Dv.z, y.z); y.w = fmaf(uq.w, Dv.w, y.w);
            *(float4*)&out[(batchRow + t0 + t) * DMODEL + d0 + c4] = y;
        }
        __syncthreads();
    }
}

// ---------------------------------------------------------------------------
// Launch
// ---------------------------------------------------------------------------
extern "C" void kernel_launch(void* const* d_in, const int* in_sizes, int n_in,
                              void* d_out, int out_size) {
    const float* x      = (const float*)d_in[0];
    const float* prompt = (const float*)d_in[1];
    const float* Wx     = (const float*)d_in[2];
    const float* Wdt    = (const float*)d_in[3];
    const float* bdt    = (const float*)d_in[4];
    const float* A_log  = (const float*)d_in[5];
    const float* Dskip  = (const float*)d_in[6];
    float* out = (float*)d_out;

    float *p_Wxq, *p_Wdtq;
    cudaGetSymbolAddress((void**)&p_Wxq,  g_Wxq);
    cudaGetSymbolAddress((void**)&p_Wdtq, g_Wdtq);

    cudaFuncSetAttribute(k_scan, cudaFuncAttributeMaxDynamicSharedMemorySize,
                         SCAN_SMEM_FLOATS * 4);

    int n4x = BL * DMODEL / 4;

    k_init<<<1, 32>>>();
    k_quant_rows<<<OCOLS, 128>>>(Wx, p_Wxq, DMODEL);
    k_quant_rows<<<DMODEL, 128>>>(Wdt, p_Wdtq, DTRANK);
    k_prep_A<<<DMODEL / 8, 128>>>(A_log);
    k_quant_D<<<1, 256>>>(Dskip);
    k_absmax_x<<<1024, 256>>>((const float4*)x, n4x);
    k_uq<<<1024, 256>>>((const float4*)x, n4x);
    k_gemm1<<<BL / 64, 320>>>(x);
    k_absmax_BC<<<64, 128>>>(prompt);
    k_gemm2<<<dim3(BL / 64, DMODEL / 128), 256>>>(bdt);
    k_absmax_dt<<<1024, 256>>>();
    k_dt_transform<<<2048, 256>>>();
    k_quant_BC<<<64, 128>>>(prompt);
    k_scan<<<128, 128, SCAN_SMEM_FLOATS * 4>>>(out);
}

// round 6
// speedup vs baseline: 1.0454x; 1.0454x over previous
#include <cuda_runtime.h>
#include <cuda_bf16.h>
#include <math.h>

// ---------------------------------------------------------------------------
// Problem constants
// ---------------------------------------------------------------------------
#define BATCH   2
#define LSEQ    4096
#define DMODEL  2048
#define BL      (BATCH * LSEQ)          // 8192
#define DTRANK  128
#define DSTATE  16
#define OCOLS   (DTRANK + 2 * DSTATE)   // 160
#define LOG2E   1.4426950408889634f

// ---------------------------------------------------------------------------
// Scratch (device globals; allocation-free per harness rules)
// ---------------------------------------------------------------------------
__device__ float    g_Wxq [OCOLS * DMODEL];      // quantized Wx
__device__ float    g_Wdtq[DMODEL * DTRANK];     // quantized Wdt
__device__ float    g_A2  [DMODEL * DSTATE];     // -exp(fq(A_log)) * log2(e)
__device__ float    g_Dq  [DMODEL];              // fq(Dskip)
__device__ float    g_xdbl[BL * OCOLS];          // GEMM1 out
__device__ float    g_dt  [BL * DMODEL];         // GEMM2 out -> softplus(fq) in place
__device__ float    g_uq  [BL * DMODEL];         // fq(x)
__device__ float    g_Bq  [BL * DSTATE];
__device__ float    g_Cq  [BL * DSTATE];
__device__ unsigned g_maxbits[4];                // 0:|x| 1:|dts| 2:|Bs| 3:|Cs+prompt|

// ---------------------------------------------------------------------------
// Helpers
// ---------------------------------------------------------------------------
__device__ __forceinline__ float ex2f(float x) {
    float r;
    asm("ex2.approx.ftz.f32 %0, %1;" : "=f"(r) : "f"(x));
    return r;
}

__device__ __forceinline__ float fq_val(float x, float s) {
    // clip(round(x/s), -128, 127) * s ; rintf = round-half-even (jnp.round)
    return fminf(fmaxf(rintf(x / s), -128.0f), 127.0f) * s;
}

// block-wide max reduction; all threads receive the result
__device__ __forceinline__ float block_max(float v) {
    __shared__ float red[32];
    __syncthreads();
    #pragma unroll
    for (int o = 16; o; o >>= 1)
        v = fmaxf(v, __shfl_xor_sync(0xffffffffu, v, o));
    int w = threadIdx.x >> 5, nl = threadIdx.x & 31;
    if (nl == 0) red[w] = v;
    __syncthreads();
    int nw = blockDim.x >> 5;
    if (w == 0) {
        float m = (nl < nw) ? red[nl] : 0.0f;
        #pragma unroll
        for (int o = 16; o; o >>= 1)
            m = fmaxf(m, __shfl_xor_sync(0xffffffffu, m, o));
        if (nl == 0) red[0] = m;
    }
    __syncthreads();
    return red[0];
}

__device__ __forceinline__ void cp16(void* dst, const void* src) {
    unsigned s = (unsigned)__cvta_generic_to_shared(dst);
    asm volatile("cp.async.cg.shared.global [%0], [%1], 16;" :: "r"(s), "l"(src));
}

// ---------------------------------------------------------------------------
// Prep kernels
// ---------------------------------------------------------------------------
__global__ void k_init() {
    if (threadIdx.x < 4) g_maxbits[threadIdx.x] = 0u;
}

// per-output-channel weight fake-quant: one block per row
__global__ void k_quant_rows(const float* __restrict__ src, float* __restrict__ dst, int K) {
    int row = blockIdx.x;
    const float* s = src + (size_t)row * K;
    float m = 0.0f;
    for (int i = threadIdx.x; i < K; i += blockDim.x) m = fmaxf(m, fabsf(s[i]));
    m = block_max(m);
    float sc = fmaxf(m / 127.0f, 1e-8f);
    float* d = dst + (size_t)row * K;
    for (int i = threadIdx.x; i < K; i += blockDim.x) d[i] = fq_val(s[i], sc);
}

// A_log: per-row (16 cols) quant, then A2 = -exp(q)*log2e.  8 rows per block.
__global__ void k_prep_A(const float* __restrict__ A_log) {
    int r = blockIdx.x * 8 + (threadIdx.x >> 4);
    int j = threadIdx.x & 15;
    float v = A_log[r * DSTATE + j];
    float m = fabsf(v);
    #pragma unroll
    for (int o = 8; o; o >>= 1) m = fmaxf(m, __shfl_xor_sync(0xffffffffu, m, o));
    float s = fmaxf(m / 127.0f, 1e-8f);
    float q = fq_val(v, s);
    g_A2[r * DSTATE + j] = -expf(q) * LOG2E;
}

__global__ void k_quant_D(const float* __restrict__ Dskip) {
    float m = 0.0f;
    for (int i = threadIdx.x; i < DMODEL; i += blockDim.x) m = fmaxf(m, fabsf(Dskip[i]));
    m = block_max(m);
    float s = fmaxf(m / 127.0f, 1e-8f);
    for (int i = threadIdx.x; i < DMODEL; i += blockDim.x) g_Dq[i] = fq_val(Dskip[i], s);
}

// ---------------------------------------------------------------------------
// Abs-max passes (atomicMax on float bit pattern; all values >= 0)
// ---------------------------------------------------------------------------
__device__ __forceinline__ void absmax_body(const float4* __restrict__ p, int n4, int slot) {
    float m = 0.0f;
    for (int i = blockIdx.x * blockDim.x + threadIdx.x; i < n4; i += gridDim.x * blockDim.x) {
        float4 v = p[i];
        m = fmaxf(m, fmaxf(fmaxf(fabsf(v.x), fabsf(v.y)), fmaxf(fabsf(v.z), fabsf(v.w))));
    }
    m = block_max(m);
    if (threadIdx.x == 0) atomicMax(&g_maxbits[slot], __float_as_uint(m));
}

__global__ void k_absmax_x(const float4* __restrict__ x, int n4) { absmax_body(x, n4, 0); }
__global__ void k_absmax_dt() { absmax_body((const float4*)g_dt, BL * DMODEL / 4, 1); }

__global__ void k_absmax_BC(const float* __restrict__ prompt) {
    int row = blockIdx.x * blockDim.x + threadIdx.x;   // 64*128 = 8192 rows
    const float* xr = g_xdbl + (size_t)row * OCOLS;
    const float* pr = prompt + (size_t)row * DSTATE;
    float mB = 0.0f, mC = 0.0f;
    #pragma unroll
    for (int j = 0; j < DSTATE; j += 4) {
        float4 bv = *(const float4*)&xr[DTRANK + j];
        float4 cv = *(const float4*)&xr[DTRANK + DSTATE + j];
        float4 pv = *(const float4*)&pr[j];
        mB = fmaxf(mB, fmaxf(fmaxf(fabsf(bv.x), fabsf(bv.y)), fmaxf(fabsf(bv.z), fabsf(bv.w))));
        float c0 = cv.x + pv.x, c1 = cv.y + pv.y, c2 = cv.z + pv.z, c3 = cv.w + pv.w;
        mC = fmaxf(mC, fmaxf(fmaxf(fabsf(c0), fabsf(c1)), fmaxf(fabsf(c2), fabsf(c3))));
    }
    float rB = block_max(mB);
    if (threadIdx.x == 0) atomicMax(&g_maxbits[2], __float_as_uint(rB));
    float rC = block_max(mC);
    if (threadIdx.x == 0) atomicMax(&g_maxbits[3], __float_as_uint(rC));
}

// ---------------------------------------------------------------------------
// Elementwise quant passes
// ---------------------------------------------------------------------------
__global__ void k_uq(const float4* __restrict__ x, int n4) {
    float s = fmaxf(__uint_as_float(g_maxbits[0]) / 127.0f, 1e-8f);
    float4* o = (float4*)g_uq;
    for (int i = blockIdx.x * blockDim.x + threadIdx.x; i < n4; i += gridDim.x * blockDim.x) {
        float4 v = x[i];
        v.x = fq_val(v.x, s); v.y = fq_val(v.y, s);
        v.z = fq_val(v.z, s); v.w = fq_val(v.w, s);
        o[i] = v;
    }
}

__device__ __forceinline__ float softplusf(float x) {
    return fmaxf(x, 0.0f) + log1pf(expf(-fabsf(x)));
}

__global__ void k_dt_transform() {
    float s = fmaxf(__uint_as_float(g_maxbits[1]) / 127.0f, 1e-8f);
    float4* p = (float4*)g_dt;
    int n4 = BL * DMODEL / 4;
    for (int i = blockIdx.x * blockDim.x + threadIdx.x; i < n4; i += gridDim.x * blockDim.x) {
        float4 v = p[i];
        v.x = softplusf(fq_val(v.x, s)); v.y = softplusf(fq_val(v.y, s));
        v.z = softplusf(fq_val(v.z, s)); v.w = softplusf(fq_val(v.w, s));
        p[i] = v;
    }
}

__global__ void k_quant_BC(const float* __restrict__ prompt) {
    int row = blockIdx.x * blockDim.x + threadIdx.x;   // 8192 rows
    float sB = fmaxf(__uint_as_float(g_maxbits[2]) / 127.0f, 1e-8f);
    float sC = fmaxf(__uint_as_float(g_maxbits[3]) / 127.0f, 1e-8f);
    const float* xr = g_xdbl + (size_t)row * OCOLS;
    const float* pr = prompt + (size_t)row * DSTATE;
    #pragma unroll
    for (int j = 0; j < DSTATE; j += 4) {
        float4 bv = *(const float4*)&xr[DTRANK + j];
        float4 cv = *(const float4*)&xr[DTRANK + DSTATE + j];
        float4 pv = *(const float4*)&pr[j];
        float4 ob, oc;
        ob.x = fq_val(bv.x, sB); ob.y = fq_val(bv.y, sB);
        ob.z = fq_val(bv.z, sB); ob.w = fq_val(bv.w, sB);
        oc.x = fq_val(cv.x + pv.x, sC); oc.y = fq_val(cv.y + pv.y, sC);
        oc.z = fq_val(cv.z + pv.z, sC); oc.w = fq_val(cv.w + pv.w, sC);
        *(float4*)&g_Bq[(size_t)row * DSTATE + j] = ob;
        *(float4*)&g_Cq[(size_t)row * DSTATE + j] = oc;
    }
}

// ---------------------------------------------------------------------------
// GEMM1: x_dbl[8192,160] = X[8192,2048] @ Wxq[160,2048]^T
// block = 320 threads, tile 64 rows x 160 cols, K-step 32
// ---------------------------------------------------------------------------
__global__ __launch_bounds__(320, 1) void k_gemm1(const float* __restrict__ X) {
    __shared__ float As[32 * 68];    // [k][row], stride 68 (16B-aligned rows)
    __shared__ float Bs[32 * 160];   // [k][col]
    int tid = threadIdx.x;
    int tx = tid % 20;               // 8 cols each -> 160
    int ty = tid / 20;               // 4 rows each -> 64
    int r0 = blockIdx.x * 64;
    float c[4][8];
    #pragma unroll
    for (int i = 0; i < 4; i++)
        #pragma unroll
        for (int j = 0; j < 8; j++) c[i][j] = 0.0f;

    for (int k0 = 0; k0 < DMODEL; k0 += 32) {
        __syncthreads();
        for (int idx = tid; idx < 512; idx += 320) {          // A: 64 rows x 8 f4
            int r = idx >> 3, kk = (idx & 7) << 2;
            float4 v = *(const float4*)&X[(size_t)(r0 + r) * DMODEL + k0 + kk];
            As[(kk + 0) * 68 + r] = v.x; As[(kk + 1) * 68 + r] = v.y;
            As[(kk + 2) * 68 + r] = v.z; As[(kk + 3) * 68 + r] = v.w;
        }
        for (int idx = tid; idx < 1280; idx += 320) {         // B: 160 cols x 8 f4
            int cc = idx >> 3, kk = (idx & 7) << 2;
            float4 v = *(const float4*)&g_Wxq[(size_t)cc * DMODEL + k0 + kk];
            Bs[(kk + 0) * 160 + cc] = v.x; Bs[(kk + 1) * 160 + cc] = v.y;
            Bs[(kk + 2) * 160 + cc] = v.z; Bs[(kk + 3) * 160 + cc] = v.w;
        }
        __syncthreads();
        #pragma unroll
        for (int k = 0; k < 32; k++) {
            float4 a  = *(const float4*)&As[k * 68 + ty * 4];
            float4 b0 = *(const float4*)&Bs[k * 160 + tx * 8];
            float4 b1 = *(const float4*)&Bs[k * 160 + tx * 8 + 4];
            float av[4] = {a.x, a.y, a.z, a.w};
            float bv[8] = {b0.x, b0.y, b0.z, b0.w, b1.x, b1.y, b1.z, b1.w};
            #pragma unroll
            for (int i = 0; i < 4; i++)
                #pragma unroll
                for (int j = 0; j < 8; j++) c[i][j] = fmaf(av[i], bv[j], c[i][j]);
        }
    }
    #pragma unroll
    for (int i = 0; i < 4; i++) {
        float4 o0 = {c[i][0], c[i][1], c[i][2], c[i][3]};
        float4 o1 = {c[i][4], c[i][5], c[i][6], c[i][7]};
        size_t base = (size_t)(r0 + ty * 4 + i) * OCOLS + tx * 8;
        *(float4*)&g_xdbl[base]     = o0;
        *(float4*)&g_xdbl[base + 4] = o1;
    }
}

// ---------------------------------------------------------------------------
// GEMM2: dts[8192,2048] = x_dbl[:, :128] @ Wdtq[2048,128]^T + bdt
// block = 256 threads, tile 64 x 128, K-step 32 (K=128)
// ---------------------------------------------------------------------------
__global__ __launch_bounds__(256, 1) void k_gemm2(const float* __restrict__ bdt) {
    __shared__ float As[32 * 68];
    __shared__ float Bs[32 * 128];
    int tid = threadIdx.x;
    int tx = tid % 16;               // 8 cols -> 128
    int ty = tid / 16;               // 4 rows -> 64
    int r0 = blockIdx.x * 64;
    int c0 = blockIdx.y * 128;
    float c[4][8];
    #pragma unroll
    for (int i = 0; i < 4; i++)
        #pragma unroll
        for (int j = 0; j < 8; j++) c[i][j] = 0.0f;

    for (int k0 = 0; k0 < DTRANK; k0 += 32) {
        __syncthreads();
        for (int idx = tid; idx < 512; idx += 256) {          // A from x_dbl
            int r = idx >> 3, kk = (idx & 7) << 2;
            float4 v = *(const float4*)&g_xdbl[(size_t)(r0 + r) * OCOLS + k0 + kk];
            As[(kk + 0) * 68 + r] = v.x; As[(kk + 1) * 68 + r] = v.y;
            As[(kk + 2) * 68 + r] = v.z; As[(kk + 3) * 68 + r] = v.w;
        }
        for (int idx = tid; idx < 1024; idx += 256) {         // B from Wdtq
            int cc = idx >> 3, kk = (idx & 7) << 2;
            float4 v = *(const float4*)&g_Wdtq[(size_t)(c0 + cc) * DTRANK + k0 + kk];
            Bs[(kk + 0) * 128 + cc] = v.x; Bs[(kk + 1) * 128 + cc] = v.y;
            Bs[(kk + 2) * 128 + cc] = v.z; Bs[(kk + 3) * 128 + cc] = v.w;
        }
        __syncthreads();
        #pragma unroll
        for (int k = 0; k < 32; k++) {
            float4 a  = *(const float4*)&As[k * 68 + ty * 4];
            float4 b0 = *(const float4*)&Bs[k * 128 + tx * 8];
            float4 b1 = *(const float4*)&Bs[k * 128 + tx * 8 + 4];
            float av[4] = {a.x, a.y, a.z, a.w};
            float bv[8] = {b0.x, b0.y, b0.z, b0.w, b1.x, b1.y, b1.z, b1.w};
            #pragma unroll
            for (int i = 0; i < 4; i++)
                #pragma unroll
                for (int j = 0; j < 8; j++) c[i][j] = fmaf(av[i], bv[j], c[i][j]);
        }
    }
    float bias[8];
    #pragma unroll
    for (int j = 0; j < 8; j++) bias[j] = bdt[c0 + tx * 8 + j];
    #pragma unroll
    for (int i = 0; i < 4; i++) {
        float4 o0 = {c[i][0] + bias[0], c[i][1] + bias[1], c[i][2] + bias[2], c[i][3] + bias[3]};
        float4 o1 = {c[i][4] + bias[4], c[i][5] + bias[5], c[i][6] + bias[6], c[i][7] + bias[7]};
        size_t base = (size_t)(r0 + ty * 4 + i) * DMODEL + c0 + tx * 8;
        *(float4*)&g_dt[base]     = o0;
        *(float4*)&g_dt[base + 4] = o1;
    }
}

// ---------------------------------------------------------------------------
// Selective scan: 128 blocks x 128 threads. Block = 32 channels (4 lanes x 4
// states each). Double-buffered cp.async staging of 64-step tiles.
// ---------------------------------------------------------------------------
#define SCT 64
#define SCC 32
// dynamic smem layout (floats):
//   sdt[2][SCT*SCC]  @0      su[2][SCT*SCC] @4096
//   sB [2][SCT*16]   @8192   sC[2][SCT*16]  @10240
//   sy [SCT*SCC]     @12288  sD[32]         @14336
#define SCAN_SMEM_FLOATS 14368

__device__ __forceinline__ void scan_issue(float* sm, int buf, int tid,
                                           size_t rowBase, int d0) {
    float* sdt = sm + buf * (SCT * SCC);
    float* su  = sm + 4096 + buf * (SCT * SCC);
    float* sB  = sm + 8192 + buf * (SCT * 16);
    float* sC  = sm + 10240 + buf * (SCT * 16);
    #pragma unroll
    for (int i = 0; i < 4; i++) {
        int idx = tid + 128 * i;
        int t = idx >> 3, c4 = (idx & 7) << 2;
        size_t g = (rowBase + t) * DMODEL + d0 + c4;
        cp16(&sdt[t * SCC + c4], &g_dt[g]);
        cp16(&su [t * SCC + c4], &g_uq[g]);
    }
    #pragma unroll
    for (int i = 0; i < 2; i++) {
        int idx = tid + 128 * i;
        int t = idx >> 2, j4 = (idx & 3) << 2;
        size_t g = (rowBase + t) * DSTATE + j4;
        cp16(&sB[t * 16 + j4], &g_Bq[g]);
        cp16(&sC[t * 16 + j4], &g_Cq[g]);
    }
    asm volatile("cp.async.commit_group;\n" ::: "memory");
}

__global__ __launch_bounds__(128, 1) void k_scan(float* __restrict__ out) {
    extern __shared__ float sm[];
    float* sy = sm + 12288;
    float* sD = sm + 14336;
    int tid = threadIdx.x;
    int b  = blockIdx.x >> 6;            // 128 blocks: 64 per batch
    int d0 = (blockIdx.x & 63) * SCC;
    int ch = tid >> 2, ln = tid & 3;
    int d  = d0 + ch;
    float4 A2r = *(const float4*)&g_A2[d * DSTATE + ln * 4];
    if (tid < SCC) sD[tid] = g_Dq[d0 + tid];
    float h0 = 0.f, h1 = 0.f, h2 = 0.f, h3 = 0.f;
    size_t batchRow = (size_t)b * LSEQ;

    scan_issue(sm, 0, tid, batchRow, d0);

    for (int tile = 0; tile < LSEQ / SCT; tile++) {
        int buf = tile & 1;
        int t0 = tile * SCT;
        if (tile < LSEQ / SCT - 1) {
            scan_issue(sm, buf ^ 1, tid, batchRow + t0 + SCT, d0);
            asm volatile("cp.async.wait_group 1;\n" ::: "memory");
        } else {
            asm volatile("cp.async.wait_group 0;\n" ::: "memory");
        }
        __syncthreads();

        const float* dtp = sm + buf * (SCT * SCC);
        const float* up  = sm + 4096 + buf * (SCT * SCC);
        const float* Bp  = sm + 8192 + buf * (SCT * 16);
        const float* Cp  = sm + 10240 + buf * (SCT * 16);

        #pragma unroll 4
        for (int t = 0; t < SCT; t++) {
            float dtv = dtp[t * SCC + ch];
            float uq  = up [t * SCC + ch];
            float du  = dtv * uq;
            float4 Bv = *(const float4*)&Bp[t * 16 + ln * 4];
            float4 Cv = *(const float4*)&Cp[t * 16 + ln * 4];
            h0 = fmaf(ex2f(dtv * A2r.x), h0, du * Bv.x);
            h1 = fmaf(ex2f(dtv * A2r.y), h1, du * Bv.y);
            h2 = fmaf(ex2f(dtv * A2r.z), h2, du * Bv.z);
            h3 = fmaf(ex2f(dtv * A2r.w), h3, du * Bv.w);
            float y = fmaf(h3, Cv.w, fmaf(h2, Cv.z, fmaf(h1, Cv.y, h0 * Cv.x)));
            y += __shfl_xor_sync(0xffffffffu, y, 1);
            y += __shfl_xor_sync(0xffffffffu, y, 2);
            if (ln == 0) sy[t * SCC + ch] = y;
        }
        __syncthreads();

        // coalesced store: out = y + u_q * D_q
        #pragma unroll
        for (int i = 0; i < 4; i++) {
            int idx = tid + 128 * i;
            int t = idx >> 3, c4 = (idx & 7) << 2;
            float4 y  = *(const float4*)&sy[t * SCC + c4];
            float4 uq = *(const float4*)&up[t * SCC + c4];
            float4 Dv = *(const float4*)&sD[c4];
            y.x = fmaf(uq.x, Dv.x, y.x); y.y = fmaf(uq.y, Dv.y, y.y);
            y.z = fmaf(uq.z, Dv.z, y.z); y.w = fmaf(uq.w, Dv.w, y.w);
            *(float4*)&out[(batchRow + t0 + t) * DMODEL + d0 + c4] = y;
        }
        __syncthreads();
    }
}

// ---------------------------------------------------------------------------
// Launch
// ---------------------------------------------------------------------------
extern "C" void kernel_launch(void* const* d_in, const int* in_sizes, int n_in,
                              void* d_out, int out_size) {
    const float* x      = (const float*)d_in[0];
    const float* prompt = (const float*)d_in[1];
    const float* Wx     = (const float*)d_in[2];
    const float* Wdt    = (const float*)d_in[3];
    const float* bdt    = (const float*)d_in[4];
    const float* A_log  = (const float*)d_in[5];
    const float* Dskip  = (const float*)d_in[6];
    float* out = (float*)d_out;

    float *p_Wxq, *p_Wdtq;
    cudaGetSymbolAddress((void**)&p_Wxq,  g_Wxq);
    cudaGetSymbolAddress((void**)&p_Wdtq, g_Wdtq);

    cudaFuncSetAttribute(k_scan, cudaFuncAttributeMaxDynamicSharedMemorySize,
                         SCAN_SMEM_FLOATS * 4);

    int n4x = BL * DMODEL / 4;

    k_init<<<1, 32>>>();
    k_quant_rows<<<OCOLS, 128>>>(Wx, p_Wxq, DMODEL);
    k_quant_rows<<<DMODEL, 128>>>(Wdt, p_Wdtq, DTRANK);
    k_prep_A<<<DMODEL / 8, 128>>>(A_log);
    k_quant_D<<<1, 256>>>(Dskip);
    k_absmax_x<<<1024, 256>>>((const float4*)x, n4x);
    k_uq<<<1024, 256>>>((const float4*)x, n4x);
    k_gemm1<<<BL / 64, 320>>>(x);
    k_absmax_BC<<<64, 128>>>(prompt);
    k_gemm2<<<dim3(BL / 64, DMODEL / 128), 256>>>(bdt);
    k_absmax_dt<<<1024, 256>>>();
    k_dt_transform<<<2048, 256>>>();
    k_quant_BC<<<64, 128>>>(prompt);
    k_scan<<<128, 128, SCAN_SMEM_FLOATS * 4>>>(out);
}

// round 8
// speedup vs baseline: 1.8150x; 1.7361x over previous
#include <cuda_runtime.h>
#include <cuda_bf16.h>
#include <math.h>
#include <stdint.h>

#define BATCH   2
#define LSEQ    4096
#define DMODEL  2048
#define BL      (BATCH * LSEQ)
#define DTRANK  128
#define DSTATE  16
#define OCOLS   160
#define LOG2E   1.4426950408889634f

// ---- scratch ----
__device__ __align__(16) __nv_bfloat16 g_Wx_hi [OCOLS * DMODEL];
__device__ __align__(16) __nv_bfloat16 g_Wx_lo [OCOLS * DMODEL];
__device__ __align__(16) __nv_bfloat16 g_Wdt_hi[DMODEL * DTRANK];
__device__ __align__(16) __nv_bfloat16 g_Wdt_lo[DMODEL * DTRANK];
__device__ __align__(16) __nv_bfloat16 g_xhi [BL * DMODEL];
__device__ __align__(16) __nv_bfloat16 g_xlo [BL * DMODEL];
__device__ __align__(16) __nv_bfloat16 g_xd_hi[BL * DTRANK];
__device__ __align__(16) __nv_bfloat16 g_xd_lo[BL * DTRANK];
__device__ __align__(16) float g_A2 [DMODEL * DSTATE];
__device__ __align__(16) float g_Dq [DMODEL];
__device__ __align__(16) float g_dt [BL * DMODEL];
__device__ __align__(16) float g_uq [BL * DMODEL];
__device__ __align__(16) float g_Braw[BL * DSTATE];
__device__ __align__(16) float g_Craw[BL * DSTATE];
__device__ __align__(16) float g_Bq [BL * DSTATE];
__device__ __align__(16) float g_Cq [BL * DSTATE];
__device__ unsigned g_maxbits[4];   // 0:|x| 1:|dts| 2:|B| 3:|C+prompt|

// ---- helpers ----
__device__ __forceinline__ float ex2f(float x){ float r; asm("ex2.approx.ftz.f32 %0,%1;":"=f"(r):"f"(x)); return r; }
__device__ __forceinline__ float fq_val(float x, float s){
    return fminf(fmaxf(rintf(x / s), -128.0f), 127.0f) * s;
}
__device__ __forceinline__ float block_max(float v){
    __shared__ float red[32];
    __syncthreads();
    #pragma unroll
    for (int o = 16; o; o >>= 1) v = fmaxf(v, __shfl_xor_sync(~0u, v, o));
    int w = threadIdx.x >> 5, nl = threadIdx.x & 31;
    if (nl == 0) red[w] = v;
    __syncthreads();
    int nw = blockDim.x >> 5;
    if (w == 0){
        float m = (nl < nw) ? red[nl] : 0.0f;
        #pragma unroll
        for (int o = 16; o; o >>= 1) m = fmaxf(m, __shfl_xor_sync(~0u, m, o));
        if (nl == 0) red[0] = m;
    }
    __syncthreads();
    return red[0];
}
__device__ __forceinline__ void cp16(void* dst, const void* src){
    unsigned s = (unsigned)__cvta_generic_to_shared(dst);
    asm volatile("cp.async.cg.shared.global [%0], [%1], 16;" :: "r"(s), "l"(src));
}
__device__ __forceinline__ float warp_max(float v){
    #pragma unroll
    for (int o = 16; o; o >>= 1) v = fmaxf(v, __shfl_xor_sync(~0u, v, o));
    return v;
}
__device__ __forceinline__ void ldsm4(unsigned* r, unsigned addr){
    asm volatile("ldmatrix.sync.aligned.m8n8.x4.shared.b16 {%0,%1,%2,%3}, [%4];"
        : "=r"(r[0]), "=r"(r[1]), "=r"(r[2]), "=r"(r[3]) : "r"(addr));
}
__device__ __forceinline__ void mma16816(float* c, const unsigned* a, unsigned b0, unsigned b1){
    asm volatile("mma.sync.aligned.m16n8k16.row.col.f32.bf16.bf16.f32 "
        "{%0,%1,%2,%3}, {%4,%5,%6,%7}, {%8,%9}, {%0,%1,%2,%3};"
        : "+f"(c[0]), "+f"(c[1]), "+f"(c[2]), "+f"(c[3])
        : "r"(a[0]), "r"(a[1]), "r"(a[2]), "r"(a[3]), "r"(b0), "r"(b1));
}
__device__ __forceinline__ unsigned pk2(float a, float b){
    __nv_bfloat162 h = __floats2bfloat162_rn(a, b);
    return *(unsigned*)&h;
}

// ---- prep kernels ----
__global__ void k_init(){ if (threadIdx.x < 4) g_maxbits[threadIdx.x] = 0u; }

template<int W>
__global__ void k_qsplit(const float* __restrict__ src, int K){
    __nv_bfloat16* hi = W ? g_Wdt_hi : g_Wx_hi;
    __nv_bfloat16* lo = W ? g_Wdt_lo : g_Wx_lo;
    int row = blockIdx.x;
    const float* s = src + (size_t)row * K;
    float m = 0.0f;
    for (int i = threadIdx.x; i < K; i += blockDim.x) m = fmaxf(m, fabsf(s[i]));
    m = block_max(m);
    float sc = fmaxf(m / 127.0f, 1e-8f);
    for (int i = threadIdx.x; i < K; i += blockDim.x){
        float q = fq_val(s[i], sc);
        __nv_bfloat16 h = __float2bfloat16(q);
        hi[(size_t)row * K + i] = h;
        lo[(size_t)row * K + i] = __float2bfloat16(q - __bfloat162float(h));
    }
}

__global__ void k_prep_A(const float* __restrict__ A_log){
    int r = blockIdx.x * 8 + (threadIdx.x >> 4), j = threadIdx.x & 15;
    float v = A_log[r * DSTATE + j];
    float m = fabsf(v);
    #pragma unroll
    for (int o = 8; o; o >>= 1) m = fmaxf(m, __shfl_xor_sync(~0u, m, o));
    g_A2[r * DSTATE + j] = -expf(fq_val(v, fmaxf(m / 127.0f, 1e-8f))) * LOG2E;
}

__global__ void k_quant_D(const float* __restrict__ Dskip){
    float m = 0.0f;
    for (int i = threadIdx.x; i < DMODEL; i += blockDim.x) m = fmaxf(m, fabsf(Dskip[i]));
    m = block_max(m);
    float s = fmaxf(m / 127.0f, 1e-8f);
    for (int i = threadIdx.x; i < DMODEL; i += blockDim.x) g_Dq[i] = fq_val(Dskip[i], s);
}

__global__ void k_absmax_x(const float4* __restrict__ x, int n4){
    float m = 0.0f;
    for (int i = blockIdx.x * blockDim.x + threadIdx.x; i < n4; i += gridDim.x * blockDim.x){
        float4 v = x[i];
        m = fmaxf(m, fmaxf(fmaxf(fabsf(v.x), fabsf(v.y)), fmaxf(fabsf(v.z), fabsf(v.w))));
    }
    m = block_max(m);
    if (threadIdx.x == 0) atomicMax(&g_maxbits[0], __float_as_uint(m));
}

// u_q = fq(x) and split raw x to bf16 hi/lo for GEMM1
__global__ void k_uq_split(const float4* __restrict__ x, int n4){
    float s = fmaxf(__uint_as_float(g_maxbits[0]) / 127.0f, 1e-8f);
    float4* o = (float4*)g_uq;
    uint2* oh = (uint2*)g_xhi; uint2* ol = (uint2*)g_xlo;
    for (int i = blockIdx.x * blockDim.x + threadIdx.x; i < n4; i += gridDim.x * blockDim.x){
        float4 v = x[i];
        float4 q = { fq_val(v.x, s), fq_val(v.y, s), fq_val(v.z, s), fq_val(v.w, s) };
        o[i] = q;
        __nv_bfloat162 h0 = __floats2bfloat162_rn(v.x, v.y);
        __nv_bfloat162 h1 = __floats2bfloat162_rn(v.z, v.w);
        uint2 hh = { *(unsigned*)&h0, *(unsigned*)&h1 };
        oh[i] = hh;
        __nv_bfloat162 l0 = __floats2bfloat162_rn(v.x - __bfloat162float(h0.x), v.y - __bfloat162float(h0.y));
        __nv_bfloat162 l1 = __floats2bfloat162_rn(v.z - __bfloat162float(h1.x), v.w - __bfloat162float(h1.y));
        uint2 ll = { *(unsigned*)&l0, *(unsigned*)&l1 };
        ol[i] = ll;
    }
}

__device__ __forceinline__ float softplusf(float x){
    return fmaxf(x, 0.0f) + log1pf(expf(-fabsf(x)));
}
__global__ void k_dt_transform(){
    float s = fmaxf(__uint_as_float(g_maxbits[1]) / 127.0f, 1e-8f);
    float4* p = (float4*)g_dt;
    int n4 = BL * DMODEL / 4;
    for (int i = blockIdx.x * blockDim.x + threadIdx.x; i < n4; i += gridDim.x * blockDim.x){
        float4 v = p[i];
        v.x = softplusf(fq_val(v.x, s)); v.y = softplusf(fq_val(v.y, s));
        v.z = softplusf(fq_val(v.z, s)); v.w = softplusf(fq_val(v.w, s));
        p[i] = v;
    }
}

__global__ void k_quant_BC(){
    int row = blockIdx.x * blockDim.x + threadIdx.x;
    float sB = fmaxf(__uint_as_float(g_maxbits[2]) / 127.0f, 1e-8f);
    float sC = fmaxf(__uint_as_float(g_maxbits[3]) / 127.0f, 1e-8f);
    #pragma unroll
    for (int j = 0; j < DSTATE; j += 4){
        float4 b = *(const float4*)&g_Braw[(size_t)row * DSTATE + j];
        float4 c = *(const float4*)&g_Craw[(size_t)row * DSTATE + j];
        b.x = fq_val(b.x, sB); b.y = fq_val(b.y, sB); b.z = fq_val(b.z, sB); b.w = fq_val(b.w, sB);
        c.x = fq_val(c.x, sC); c.y = fq_val(c.y, sC); c.z = fq_val(c.z, sC); c.w = fq_val(c.w, sC);
        *(float4*)&g_Bq[(size_t)row * DSTATE + j] = b;
        *(float4*)&g_Cq[(size_t)row * DSTATE + j] = c;
    }
}

// ---------------------------------------------------------------------------
// bf16 hi/lo split GEMM via mma.sync.m16n8k16 (target-independent PTX).
// CTA: 128 thr / 4 warps. M-tile 64 (16 rows/warp), full N per tile.
// K-chunk 32, cp.async double-buffered, 40-bf16 padded rows (ldmatrix
// conflict-free: row*20 mod 32 distinct over 8 rows).
// MODE 0: GEMM1 X@Wx^T (N=160, K=2048). Epilogue: xd hi/lo split (cols<128),
//         raw B (128-143), C+prompt (144-159), absmax B/C.  aux = prompt.
// MODE 1: GEMM2 xd@Wdt^T + bdt (N=128 tile, K=128). Epilogue: bias, absmax,
//         f32 store to g_dt.  aux = bdt.
// ---------------------------------------------------------------------------
template<int N, int KTOT, int MODE>
__global__ __launch_bounds__(128, 1) void k_mma(const float* __restrict__ aux){
    constexpr int NB  = N / 8;      // n-blocks
    constexpr int NP  = NB / 2;     // ldmatrix x4 pairs
    constexpr int NCH = KTOT / 32;
    constexpr int ASZ = 64 * 40;    // bf16 per half
    constexpr int BSZ = N * 40;
    constexpr int BUFSZ = 2 * ASZ + 2 * BSZ;
    extern __shared__ __nv_bfloat16 sm[];

    int tid = threadIdx.x, wid = tid >> 5, lane = tid & 31;
    int r0 = blockIdx.x * 64;
    int c0 = MODE ? blockIdx.y * N : 0;
    const __nv_bfloat16* Ah = MODE ? g_xd_hi : g_xhi;
    const __nv_bfloat16* Al = MODE ? g_xd_lo : g_xlo;
    const __nv_bfloat16* Bh = MODE ? g_Wdt_hi : g_Wx_hi;
    const __nv_bfloat16* Bl = MODE ? g_Wdt_lo : g_Wx_lo;

    float acc[NB][4];
    #pragma unroll
    for (int n = 0; n < NB; n++){ acc[n][0]=0.f; acc[n][1]=0.f; acc[n][2]=0.f; acc[n][3]=0.f; }

    auto fill = [&](int c, int buf){
        __nv_bfloat16* base = sm + buf * BUFSZ;
        #pragma unroll
        for (int i = tid; i < 256; i += 128){
            int r = i >> 2, ch = i & 3;
            size_t g = (size_t)(r0 + r) * KTOT + c * 32 + ch * 8;
            unsigned off = r * 40 + ch * 8;
            cp16(base + off, Ah + g);
            cp16(base + ASZ + off, Al + g);
        }
        for (int i = tid; i < N * 4; i += 128){
            int r = i >> 2, ch = i & 3;
            size_t g = (size_t)(c0 + r) * KTOT + c * 32 + ch * 8;
            unsigned off = r * 40 + ch * 8;
            cp16(base + 2 * ASZ + off, Bh + g);
            cp16(base + 2 * ASZ + BSZ + off, Bl + g);
        }
        asm volatile("cp.async.commit_group;" ::: "memory");
    };

    fill(0, 0);
    int j = lane >> 3, r8 = lane & 7;
    int lrow = r8 + (j & 1) * 8;          // row within 16-row matrix group
    int lk8  = (j >> 1) * 8;              // k-offset 0/8 within kstep

    for (int c = 0; c < NCH; c++){
        int buf = c & 1;
        if (c + 1 < NCH) fill(c + 1, buf ^ 1);
        if (c + 1 < NCH) asm volatile("cp.async.wait_group 1;" ::: "memory");
        else             asm volatile("cp.async.wait_group 0;" ::: "memory");
        __syncthreads();
        unsigned base = (unsigned)__cvta_generic_to_shared(sm + buf * BUFSZ);
        #pragma unroll
        for (int ks = 0; ks < 2; ks++){
            unsigned ah[4], al[4];
            unsigned aaddr = base + ((wid * 16 + lrow) * 40 + ks * 16 + lk8) * 2;
            ldsm4(ah, aaddr);
            ldsm4(al, aaddr + ASZ * 2);
            #pragma unroll
            for (int p = 0; p < NP; p++){
                unsigned baddr = base + (2 * ASZ + (p * 16 + lrow) * 40 + ks * 16 + lk8) * 2;
                unsigned bh4[4], bl4[4];
                ldsm4(bh4, baddr);
                ldsm4(bl4, baddr + BSZ * 2);
                // r0=b0(2p) r1=b0(2p+1) r2=b1(2p) r3=b1(2p+1)
                mma16816(acc[2*p],   ah, bh4[0], bh4[2]);
                mma16816(acc[2*p],   ah, bl4[0], bl4[2]);
                mma16816(acc[2*p],   al, bh4[0], bh4[2]);
                mma16816(acc[2*p+1], ah, bh4[1], bh4[3]);
                mma16816(acc[2*p+1], ah, bl4[1], bl4[3]);
                mma16816(acc[2*p+1], al, bh4[1], bh4[3]);
            }
        }
        __syncthreads();
    }

    // ---- epilogue ----
    int g = lane >> 2, tig = lane & 3;
    int row0 = r0 + wid * 16 + g;
    int row1 = row0 + 8;
    if (MODE == 0){
        float mb = 0.f, mc = 0.f;
        #pragma unroll
        for (int n = 0; n < NB; n++){
            int col = n * 8 + tig * 2;
            if (n < 16){
                *(unsigned*)&g_xd_hi[(size_t)row0 * DTRANK + col] = pk2(acc[n][0], acc[n][1]);
                *(unsigned*)&g_xd_hi[(size_t)row1 * DTRANK + col] = pk2(acc[n][2], acc[n][3]);
                float h00 = __bfloat162float(__float2bfloat16(acc[n][0]));
                float h01 = __bfloat162float(__float2bfloat16(acc[n][1]));
                float h10 = __bfloat162float(__float2bfloat16(acc[n][2]));
                float h11 = __bfloat162float(__float2bfloat16(acc[n][3]));
                *(unsigned*)&g_xd_lo[(size_t)row0 * DTRANK + col] = pk2(acc[n][0] - h00, acc[n][1] - h01);
                *(unsigned*)&g_xd_lo[(size_t)row1 * DTRANK + col] = pk2(acc[n][2] - h10, acc[n][3] - h11);
            } else if (n < 18){
                int bc = col - 128;
                float2 v0 = { acc[n][0], acc[n][1] };
                float2 v1 = { acc[n][2], acc[n][3] };
                *(float2*)&g_Braw[(size_t)row0 * DSTATE + bc] = v0;
                *(float2*)&g_Braw[(size_t)row1 * DSTATE + bc] = v1;
                mb = fmaxf(mb, fmaxf(fmaxf(fabsf(v0.x), fabsf(v0.y)), fmaxf(fabsf(v1.x), fabsf(v1.y))));
            } else {
                int cc = col - 144;
                float2 p0 = *(const float2*)&aux[(size_t)row0 * DSTATE + cc];
                float2 p1 = *(const float2*)&aux[(size_t)row1 * DSTATE + cc];
                float2 v0 = { acc[n][0] + p0.x, acc[n][1] + p0.y };
                float2 v1 = { acc[n][2] + p1.x, acc[n][3] + p1.y };
                *(float2*)&g_Craw[(size_t)row0 * DSTATE + cc] = v0;
                *(float2*)&g_Craw[(size_t)row1 * DSTATE + cc] = v1;
                mc = fmaxf(mc, fmaxf(fmaxf(fabsf(v0.x), fabsf(v0.y)), fmaxf(fabsf(v1.x), fabsf(v1.y))));
            }
        }
        mb = warp_max(mb); mc = warp_max(mc);
        if (lane == 0){
            atomicMax(&g_maxbits[2], __float_as_uint(mb));
            atomicMax(&g_maxbits[3], __float_as_uint(mc));
        }
    } else {
        float mx = 0.f;
        #pragma unroll
        for (int n = 0; n < NB; n++){
            int col = c0 + n * 8 + tig * 2;
            float b0v = aux[col], b1v = aux[col + 1];
            float2 v0 = { acc[n][0] + b0v, acc[n][1] + b1v };
            float2 v1 = { acc[n][2] + b0v, acc[n][3] + b1v };
            *(float2*)&g_dt[(size_t)row0 * DMODEL + col] = v0;
            *(float2*)&g_dt[(size_t)row1 * DMODEL + col] = v1;
            mx = fmaxf(mx, fmaxf(fmaxf(fabsf(v0.x), fabsf(v0.y)), fmaxf(fabsf(v1.x), fabsf(v1.y))));
        }
        mx = warp_max(mx);
        if (lane == 0) atomicMax(&g_maxbits[1], __float_as_uint(mx));
    }
}

// ---------------------------------------------------------------------------
// Selective scan (unchanged from the passing round-4 kernel)
// ---------------------------------------------------------------------------
#define SCT 64
#define SCC 32
#define SCAN_SMEM_FLOATS 14368

__device__ __forceinline__ void scan_issue(float* sm, int buf, int tid, size_t rowBase, int d0){
    float* sdt = sm + buf * (SCT * SCC);
    float* su  = sm + 4096 + buf * (SCT * SCC);
    float* sB  = sm + 8192 + buf * (SCT * 16);
    float* sC  = sm + 10240 + buf * (SCT * 16);
    #pragma unroll
    for (int i = 0; i < 4; i++){
        int idx = tid + 128 * i;
        int t = idx >> 3, c4 = (idx & 7) << 2;
        size_t g = (rowBase + t) * DMODEL + d0 + c4;
        cp16(&sdt[t * SCC + c4], &g_dt[g]);
        cp16(&su [t * SCC + c4], &g_uq[g]);
    }
    #pragma unroll
    for (int i = 0; i < 2; i++){
        int idx = tid + 128 * i;
        int t = idx >> 2, j4 = (idx & 3) << 2;
        size_t g = (rowBase + t) * DSTATE + j4;
        cp16(&sB[t * 16 + j4], &g_Bq[g]);
        cp16(&sC[t * 16 + j4], &g_Cq[g]);
    }
    asm volatile("cp.async.commit_group;\n" ::: "memory");
}

__global__ __launch_bounds__(128, 1) void k_scan(float* __restrict__ out){
    extern __shared__ float smf[];
    float* sy = smf + 12288;
    float* sD = smf + 14336;
    int tid = threadIdx.x;
    int b  = blockIdx.x >> 6;
    int d0 = (blockIdx.x & 63) * SCC;
    int ch = tid >> 2, ln = tid & 3;
    float4 A2r = *(const float4*)&g_A2[(d0 + ch) * DSTATE + ln * 4];
    if (tid < SCC) sD[tid] = g_Dq[d0 + tid];
    float h0 = 0.f, h1 = 0.f, h2 = 0.f, h3 = 0.f;
    size_t batchRow = (size_t)b * LSEQ;

    scan_issue(smf, 0, tid, batchRow, d0);
    for (int tile = 0; tile < LSEQ / SCT; tile++){
        int buf = tile & 1, t0 = tile * SCT;
        if (tile < LSEQ / SCT - 1){
            scan_issue(smf, buf ^ 1, tid, batchRow + t0 + SCT, d0);
            asm volatile("cp.async.wait_group 1;\n" ::: "memory");
        } else {
            asm volatile("cp.async.wait_group 0;\n" ::: "memory");
        }
        __syncthreads();
        const float* dtp = smf + buf * (SCT * SCC);
        const float* up  = smf + 4096 + buf * (SCT * SCC);
        const float* Bp  = smf + 8192 + buf * (SCT * 16);
        const float* Cp  = smf + 10240 + buf * (SCT * 16);
        #pragma unroll 4
        for (int t = 0; t < SCT; t++){
            float dtv = dtp[t * SCC + ch];
            float du  = dtv * up[t * SCC + ch];
            float4 Bv = *(const float4*)&Bp[t * 16 + ln * 4];
            float4 Cv = *(const float4*)&Cp[t * 16 + ln * 4];
            h0 = fmaf(ex2f(dtv * A2r.x), h0, du * Bv.x);
            h1 = fmaf(ex2f(dtv * A2r.y), h1, du * Bv.y);
            h2 = fmaf(ex2f(dtv * A2r.z), h2, du * Bv.z);
            h3 = fmaf(ex2f(dtv * A2r.w), h3, du * Bv.w);
            float y = fmaf(h3, Cv.w, fmaf(h2, Cv.z, fmaf(h1, Cv.y, h0 * Cv.x)));
            y += __shfl_xor_sync(~0u, y, 1);
            y += __shfl_xor_sync(~0u, y, 2);
            if (ln == 0) sy[t * SCC + ch] = y;
        }
        __syncthreads();
        #pragma unroll
        for (int i = 0; i < 4; i++){
            int idx = tid + 128 * i;
            int t = idx >> 3, c4 = (idx & 7) << 2;
            float4 y  = *(const float4*)&sy[t * SCC + c4];
            float4 uq = *(const float4*)&up[t * SCC + c4];
            float4 Dv = *(const float4*)&sD[c4];
            y.x = fmaf(uq.x, Dv.x, y.x); y.y = fmaf(uq.y, Dv.y, y.y);
            y.z = fmaf(uq.z, Dv.z, y.z); y.w = fmaf(uq.w, Dv.w, y.w);
            *(float4*)&out[(batchRow + t0 + t) * DMODEL + d0 + c4] = y;
        }
        __syncthreads();
    }
}

// ---------------------------------------------------------------------------
extern "C" void kernel_launch(void* const* d_in, const int* in_sizes, int n_in,
                              void* d_out, int out_size){
    const float* x      = (const float*)d_in[0];
    const float* prompt = (const float*)d_in[1];
    const float* Wx     = (const float*)d_in[2];
    const float* Wdt    = (const float*)d_in[3];
    const float* bdt    = (const float*)d_in[4];
    const float* A_log  = (const float*)d_in[5];
    const float* Dskip  = (const float*)d_in[6];
    float* out = (float*)d_out;

    const int SM1 = 2 * (2 * 64 * 40 + 2 * 160 * 40) * 2;   // 71680 B
    const int SM2 = 2 * (2 * 64 * 40 + 2 * 128 * 40) * 2;   // 61440 B
    cudaFuncSetAttribute(k_mma<160, 2048, 0>, cudaFuncAttributeMaxDynamicSharedMemorySize, SM1);
    cudaFuncSetAttribute(k_mma<128, 128, 1>,  cudaFuncAttributeMaxDynamicSharedMemorySize, SM2);
    cudaFuncSetAttribute(k_scan, cudaFuncAttributeMaxDynamicSharedMemorySize, SCAN_SMEM_FLOATS * 4);

    int n4x = BL * DMODEL / 4;
    k_init<<<1, 32>>>();
    k_qsplit<0><<<OCOLS, 128>>>(Wx, DMODEL);
    k_qsplit<1><<<DMODEL, 128>>>(Wdt, DTRANK);
    k_prep_A<<<DMODEL / 8, 128>>>(A_log);
    k_quant_D<<<1, 256>>>(Dskip);
    k_absmax_x<<<1024, 256>>>((const float4*)x, n4x);
    k_uq_split<<<1024, 256>>>((const float4*)x, n4x);
    k_mma<160, 2048, 0><<<BL / 64, 128, SM1>>>(prompt);
    k_quant_BC<<<64, 128>>>();
    k_mma<128, 128, 1><<<dim3(BL / 64, DMODEL / 128), 128, SM2>>>(bdt);
    k_dt_transform<<<2048, 256>>>();
    k_scan<<<128, 128, SCAN_SMEM_FLOATS * 4>>>(out);
}